// round 7
// baseline (speedup 1.0000x reference)
#include <cuda_runtime.h>
#include <cstdint>

// ---------------------------------------------------------------------------
// HandGNNEncoder: 2-layer GCN over fixed 21-node skeleton + mean pool.
//   y[t]   = (A_norm @ x)[t]              (sparse, <=3 nz/row, consts)
//   p[d]   = sum_t c[t]*relu(y[t]@W1+b1)[d]
//   out    = p @ W2 + b2
// One warp = 8 graphs, exactly once (single wave, 512 CTAs).
// f32x2 packed over graph pairs. W2 read via LDG/L1 (no smem staging).
// Stage-2 reads y as packed pairs via broadcast LDS.64 (no shuffles).
// ---------------------------------------------------------------------------

typedef unsigned long long ull;

__device__ __forceinline__ ull pk2(float lo, float hi) {
    ull r; asm("mov.b64 %0, {%1, %2};" : "=l"(r) : "f"(lo), "f"(hi)); return r;
}
__device__ __forceinline__ void up2(ull v, float& lo, float& hi) {
    asm("mov.b64 {%0, %1}, %2;" : "=f"(lo), "=f"(hi) : "l"(v));
}
__device__ __forceinline__ ull fma2(ull a, ull b, ull c) {
    ull d; asm("fma.rn.f32x2 %0, %1, %2, %3;" : "=l"(d) : "l"(a), "l"(b), "l"(c)); return d;
}
__device__ __forceinline__ ull add2(ull a, ull b) {
    ull d; asm("add.rn.f32x2 %0, %1, %2;" : "=l"(d) : "l"(a), "l"(b)); return d;
}

#define R2  0.70710678118654752440f
#define R3  0.57735026918962576451f
#define TH  (1.0f/3.0f)
#define W23 (R2*R3)

// (column sums of A_norm / 21) * 0.5 -- the 0.5 absorbs (h+|h|)=2*relu
__device__ __constant__ float cPoolH[21] = {
    0.5f*(1.0f + 2.0f*R2 + 3.0f*R3)/21.0f,
    0.5f/21.0f, 0.5f/21.0f, 0.5f/21.0f, 0.25f/21.0f,
    0.5f*(1.0f + W23)/21.0f,     0.5f/21.0f, 0.5f/21.0f, 0.25f/21.0f,
    0.5f*(2.0f/3.0f + W23)/21.0f,0.5f/21.0f, 0.5f/21.0f, 0.25f/21.0f,
    0.5f*(2.0f/3.0f + W23)/21.0f,0.5f/21.0f, 0.5f/21.0f, 0.25f/21.0f,
    0.5f*(1.0f/3.0f + W23)/21.0f,0.5f/21.0f, 0.5f/21.0f, 0.25f/21.0f,
};
__device__ __constant__ int cIdx[63] = {
    0,0,0,   1,0,0,   2,1,0,   3,2,0,   4,3,0,
    5,0,0,   6,5,0,   7,6,0,   8,7,0,
    9,0,5,   10,9,0,  11,10,0, 12,11,0,
    13,0,9,  14,13,0, 15,14,0, 16,15,0,
    17,0,13, 18,17,0, 19,18,0, 20,19,0
};
__device__ __constant__ float cWt[63] = {
    1.0f,0.f,0.f,   0.5f,R2,0.f,   0.5f,0.5f,0.f, 0.5f,0.5f,0.f, 0.5f,0.5f,0.f,
    0.5f,R2,0.f,    0.5f,0.5f,0.f, 0.5f,0.5f,0.f, 0.5f,0.5f,0.f,
    TH,R3,W23,      0.5f,W23,0.f,  0.5f,0.5f,0.f, 0.5f,0.5f,0.f,
    TH,R3,TH,       0.5f,W23,0.f,  0.5f,0.5f,0.f, 0.5f,0.5f,0.f,
    TH,R3,TH,       0.5f,W23,0.f,  0.5f,0.5f,0.f, 0.5f,0.5f,0.f
};

#define NWARP 8
#define THREADS 256
#define FULLMASK 0xffffffffu
#define ABSMASK 0x7fffffff7fffffffULL

__global__ __launch_bounds__(256, 4)
void gnn_kernel(const float* __restrict__ x,
                const float* __restrict__ W1,
                const float* __restrict__ b1,
                const float* __restrict__ W2,
                const float* __restrict__ b2,
                float* __restrict__ out,
                int G)
{
    // 26.5 KB smem: y buffers + pooled vectors (NO W2 staging -> occupancy)
    __shared__ __align__(16) float yxs[NWARP][21][8];   // aggregated x coord
    __shared__ __align__(16) float yys[NWARP][21][8];   // aggregated y coord
    __shared__ __align__(16) float psh[NWARP][64][8];   // p[k][graph j]

    const int tid  = threadIdx.x;
    const int lane = tid & 31;
    const int warp = tid >> 5;

    // per-lane W1/b1, duplicated into both f32x2 halves (lane owns dims {l, l+32})
    const ull w1a0d = pk2(W1[lane],      W1[lane]);
    const ull w1a1d = pk2(W1[64 + lane], W1[64 + lane]);
    const ull w1b0d = pk2(W1[32 + lane], W1[32 + lane]);
    const ull w1b1d = pk2(W1[96 + lane], W1[96 + lane]);
    const ull b1ad  = pk2(b1[lane],      b1[lane]);
    const ull b1bd  = pk2(b1[32 + lane], b1[32 + lane]);

    // stage-1 sparse row of this lane (lane == target node t)
    int s0 = 0, s1 = 0, s2 = 0;
    float aw0 = 0.f, aw1 = 0.f, aw2 = 0.f;
    if (lane < 21) {
        s0  = cIdx[lane*3];  s1  = cIdx[lane*3+1];  s2  = cIdx[lane*3+2];
        aw0 = cWt[lane*3];   aw1 = cWt[lane*3+1];   aw2 = cWt[lane*3+2];
    }

    // this warp's 8 graphs
    const int g0 = (blockIdx.x * NWARP + warp) * 8;

    // ---- stage 1: y = A_norm @ x via shuffles; write y pairs to smem ----
    {
        float yx[8], yy[8];
        #pragma unroll
        for (int h = 0; h < 2; h++) {
            float2 xv[4];
            #pragma unroll
            for (int j = 0; j < 4; j++) {
                const int g = g0 + 4*h + j;
                xv[j] = (lane < 21 && g < G)
                        ? ((const float2*)x)[(size_t)g * 21 + lane]
                        : make_float2(0.f, 0.f);
            }
            #pragma unroll
            for (int j = 0; j < 4; j++) {
                float xs0x = __shfl_sync(FULLMASK, xv[j].x, s0);
                float xs0y = __shfl_sync(FULLMASK, xv[j].y, s0);
                float xs1x = __shfl_sync(FULLMASK, xv[j].x, s1);
                float xs1y = __shfl_sync(FULLMASK, xv[j].y, s1);
                float xs2x = __shfl_sync(FULLMASK, xv[j].x, s2);
                float xs2y = __shfl_sync(FULLMASK, xv[j].y, s2);
                yx[4*h + j] = fmaf(aw2, xs2x, fmaf(aw1, xs1x, aw0 * xs0x));
                yy[4*h + j] = fmaf(aw2, xs2y, fmaf(aw1, xs1y, aw0 * xs0y));
            }
        }
        if (lane < 21) {
            *(float4*)&yxs[warp][lane][0] = make_float4(yx[0], yx[1], yx[2], yx[3]);
            *(float4*)&yxs[warp][lane][4] = make_float4(yx[4], yx[5], yx[6], yx[7]);
            *(float4*)&yys[warp][lane][0] = make_float4(yy[0], yy[1], yy[2], yy[3]);
            *(float4*)&yys[warp][lane][4] = make_float4(yy[4], yy[5], yy[6], yy[7]);
        }
    }
    __syncwarp();

    // ---- stage 2: p = c^T relu(y@W1 + b1); y pairs via broadcast LDS.64 ----
    {
        ull pA[4] = {0,0,0,0}, pB[4] = {0,0,0,0};
        #pragma unroll 7
        for (int t = 0; t < 21; t++) {
            const float ch = cPoolH[t];
            const ull ct2 = pk2(ch, ch);
            #pragma unroll
            for (int jp = 0; jp < 4; jp++) {
                const ull x2 = *(const ull*)&yxs[warp][t][2*jp];
                const ull y2 = *(const ull*)&yys[warp][t][2*jp];
                ull ha = fma2(x2, w1a0d, b1ad);
                ha = fma2(y2, w1a1d, ha);
                ha = add2(ha, ha & ABSMASK);          // 2*relu
                pA[jp] = fma2(ct2, ha, pA[jp]);       // ct2 pre-halved
                ull hb = fma2(x2, w1b0d, b1bd);
                hb = fma2(y2, w1b1d, hb);
                hb = add2(hb, hb & ABSMASK);
                pB[jp] = fma2(ct2, hb, pB[jp]);
            }
        }
        // publish p: psh[warp][k][j], k = lane / lane+32
        #pragma unroll
        for (int jp = 0; jp < 4; jp++) {
            *(ull*)&psh[warp][lane][2*jp]      = pA[jp];
            *(ull*)&psh[warp][lane + 32][2*jp] = pB[jp];
        }
    }
    __syncwarp();

    // ---- stage 3: out = p @ W2 + b2; W2 from L1 via LDG.128 ----
    ull acc[4][4];
    #pragma unroll
    for (int jp = 0; jp < 4; jp++)
        #pragma unroll
        for (int c = 0; c < 4; c++) acc[jp][c] = 0ull;

    const float4* __restrict__ W2v = (const float4*)W2;   // [64][32] float4
    #pragma unroll 8
    for (int k = 0; k < 64; k++) {
        const float4 w4 = __ldg(&W2v[k*32 + lane]);       // lane's 4 output cols
        const ull wx = pk2(w4.x, w4.x);
        const ull wy = pk2(w4.y, w4.y);
        const ull wz = pk2(w4.z, w4.z);
        const ull ww = pk2(w4.w, w4.w);
        const ulonglong2 q03 = *(const ulonglong2*)&psh[warp][k][0];  // {p0p1, p2p3}
        const ulonglong2 q47 = *(const ulonglong2*)&psh[warp][k][4];  // {p4p5, p6p7}
        acc[0][0] = fma2(q03.x, wx, acc[0][0]);
        acc[0][1] = fma2(q03.x, wy, acc[0][1]);
        acc[0][2] = fma2(q03.x, wz, acc[0][2]);
        acc[0][3] = fma2(q03.x, ww, acc[0][3]);
        acc[1][0] = fma2(q03.y, wx, acc[1][0]);
        acc[1][1] = fma2(q03.y, wy, acc[1][1]);
        acc[1][2] = fma2(q03.y, wz, acc[1][2]);
        acc[1][3] = fma2(q03.y, ww, acc[1][3]);
        acc[2][0] = fma2(q47.x, wx, acc[2][0]);
        acc[2][1] = fma2(q47.x, wy, acc[2][1]);
        acc[2][2] = fma2(q47.x, wz, acc[2][2]);
        acc[2][3] = fma2(q47.x, ww, acc[2][3]);
        acc[3][0] = fma2(q47.y, wx, acc[3][0]);
        acc[3][1] = fma2(q47.y, wy, acc[3][1]);
        acc[3][2] = fma2(q47.y, wz, acc[3][2]);
        acc[3][3] = fma2(q47.y, ww, acc[3][3]);
    }

    // ---- epilogue: unpack pairs, add b2, store float4 per graph ----
    const float4 b2v = __ldg(&((const float4*)b2)[lane]);
    #pragma unroll
    for (int jp = 0; jp < 4; jp++) {
        float lo0, hi0, lo1, hi1, lo2, hi2, lo3, hi3;
        up2(acc[jp][0], lo0, hi0);
        up2(acc[jp][1], lo1, hi1);
        up2(acc[jp][2], lo2, hi2);
        up2(acc[jp][3], lo3, hi3);
        const int ga = g0 + 2*jp, gb = ga + 1;
        if (ga < G) {
            float4 o = make_float4(lo0 + b2v.x, lo1 + b2v.y, lo2 + b2v.z, lo3 + b2v.w);
            ((float4*)out)[(size_t)ga * 32 + lane] = o;
        }
        if (gb < G) {
            float4 o = make_float4(hi0 + b2v.x, hi1 + b2v.y, hi2 + b2v.z, hi3 + b2v.w);
            ((float4*)out)[(size_t)gb * 32 + lane] = o;
        }
    }
}

extern "C" void kernel_launch(void* const* d_in, const int* in_sizes, int n_in,
                              void* d_out, int out_size) {
    const float* x  = (const float*)d_in[0];
    const float* W1 = (const float*)d_in[1];
    const float* b1 = (const float*)d_in[2];
    const float* W2 = (const float*)d_in[3];
    const float* b2 = (const float*)d_in[4];
    float* out = (float*)d_out;

    const int G = in_sizes[0] / 42;            // graphs = B*S = 32768
    const int blocks = (G + 63) / 64;          // 8 graphs/warp * 8 warps/CTA

    gnn_kernel<<<blocks, THREADS>>>(x, W1, b1, W2, b2, out, G);
}

// round 8
// speedup vs baseline: 1.2796x; 1.2796x over previous
#include <cuda_runtime.h>
#include <cstdint>

// ---------------------------------------------------------------------------
// HandGNNEncoder: 2-layer GCN over fixed 21-node skeleton + mean pool.
//   y[t] = (A_norm @ x)[t]; p = c^T relu(y@W1+b1); out = p@W2 + b2
// Stages 1-2: scalar fp32 (fma pipe). Stage 3: mma.sync bf16 hi/lo 3-pass
// (tensor pipe) with ldmatrix from swizzled smem. Warp = 16 graphs (m16).
// ---------------------------------------------------------------------------

#define R2  0.70710678118654752440f
#define R3  0.57735026918962576451f
#define TH  (1.0f/3.0f)
#define W23 (R2*R3)

__device__ __constant__ float cPool[21] = {
    (1.0f + 2.0f*R2 + 3.0f*R3)/21.0f,
    1.0f/21.0f, 1.0f/21.0f, 1.0f/21.0f, 0.5f/21.0f,
    (1.0f + W23)/21.0f,      1.0f/21.0f, 1.0f/21.0f, 0.5f/21.0f,
    (2.0f/3.0f + W23)/21.0f, 1.0f/21.0f, 1.0f/21.0f, 0.5f/21.0f,
    (2.0f/3.0f + W23)/21.0f, 1.0f/21.0f, 1.0f/21.0f, 0.5f/21.0f,
    (1.0f/3.0f + W23)/21.0f, 1.0f/21.0f, 1.0f/21.0f, 0.5f/21.0f,
};
__device__ __constant__ int cIdx[63] = {
    0,0,0,   1,0,0,   2,1,0,   3,2,0,   4,3,0,
    5,0,0,   6,5,0,   7,6,0,   8,7,0,
    9,0,5,   10,9,0,  11,10,0, 12,11,0,
    13,0,9,  14,13,0, 15,14,0, 16,15,0,
    17,0,13, 18,17,0, 19,18,0, 20,19,0
};
__device__ __constant__ float cWt[63] = {
    1.0f,0.f,0.f,   0.5f,R2,0.f,   0.5f,0.5f,0.f, 0.5f,0.5f,0.f, 0.5f,0.5f,0.f,
    0.5f,R2,0.f,    0.5f,0.5f,0.f, 0.5f,0.5f,0.f, 0.5f,0.5f,0.f,
    TH,R3,W23,      0.5f,W23,0.f,  0.5f,0.5f,0.f, 0.5f,0.5f,0.f,
    TH,R3,TH,       0.5f,W23,0.f,  0.5f,0.5f,0.f, 0.5f,0.5f,0.f,
    TH,R3,TH,       0.5f,W23,0.f,  0.5f,0.5f,0.f, 0.5f,0.5f,0.f
};

#define NWARP 8
#define THREADS 256
#define FULLMASK 0xffffffffu

// packed bf16x2: upper half = hi_f, lower half = lo_f
__device__ __forceinline__ uint32_t pkbf(float up, float lo) {
    uint32_t r;
    asm("cvt.rn.bf16x2.f32 %0, %1, %2;" : "=r"(r) : "f"(up), "f"(lo));
    return r;
}
__device__ __forceinline__ float bflo_f(uint32_t p) {   // lower bf16 -> f32
    return __uint_as_float(p << 16);
}
__device__ __forceinline__ float bfhi_f(uint32_t p) {   // upper bf16 -> f32
    return __uint_as_float(p & 0xffff0000u);
}

__device__ __forceinline__ uint32_t smem_u32(const void* p) {
    uint32_t a;
    asm("{ .reg .u64 t; cvta.to.shared.u64 t, %1; cvt.u32.u64 %0, t; }"
        : "=r"(a) : "l"(p));
    return a;
}
__device__ __forceinline__ void ldsm_x4(uint32_t* r, uint32_t addr) {
    asm volatile("ldmatrix.sync.aligned.m8n8.x4.shared.b16 {%0,%1,%2,%3}, [%4];"
                 : "=r"(r[0]), "=r"(r[1]), "=r"(r[2]), "=r"(r[3]) : "r"(addr));
}
__device__ __forceinline__ void ldsm_x2t(uint32_t& r0, uint32_t& r1, uint32_t addr) {
    asm volatile("ldmatrix.sync.aligned.m8n8.x2.trans.shared.b16 {%0,%1}, [%2];"
                 : "=r"(r0), "=r"(r1) : "r"(addr));
}
__device__ __forceinline__ void mma16816(float* d, const uint32_t* a,
                                         uint32_t b0, uint32_t b1) {
    asm volatile(
        "mma.sync.aligned.m16n8k16.row.col.f32.bf16.bf16.f32 "
        "{%0,%1,%2,%3}, {%4,%5,%6,%7}, {%8,%9}, {%0,%1,%2,%3};"
        : "+f"(d[0]), "+f"(d[1]), "+f"(d[2]), "+f"(d[3])
        : "r"(a[0]), "r"(a[1]), "r"(a[2]), "r"(a[3]), "r"(b0), "r"(b1));
}

// dynamic smem offsets (bytes)
#define OFF_WHI 0                         // W2 hi bf16 [64][128], swizzled, 16KB
#define OFF_WLO 16384                     // W2 lo
#define OFF_AHI 32768                     // per-warp A hi [16][64] bf16, 2KB each
#define OFF_ALO 49152                     // per-warp A lo
#define OFF_YX  65536                     // float yx[8][21][16] = 10752B
#define OFF_YY  76288
#define DYN_SMEM 87040

__global__ __launch_bounds__(256, 2)
void gnn_kernel(const float* __restrict__ x,
                const float* __restrict__ W1,
                const float* __restrict__ b1,
                const float* __restrict__ W2,
                const float* __restrict__ b2,
                float* __restrict__ out,
                int G)
{
    extern __shared__ __align__(16) char smp[];
    const uint32_t sbase = smem_u32(smp);

    const int tid  = threadIdx.x;
    const int lane = tid & 31;
    const int warp = tid >> 5;

    // ---- prologue: W2 -> bf16 hi/lo into swizzled smem [k][n], 256B rows ----
    // pair i: k = i>>6, n2 = i&63 (cols 2*n2, 2*n2+1); W2 pair idx == i.
    for (int i = tid; i < 4096; i += THREADS) {
        const int k = i >> 6, n2 = i & 63;
        const float2 f = ((const float2*)W2)[i];
        const uint32_t hp = pkbf(f.y, f.x);
        const float rx = f.x - bflo_f(hp);
        const float ry = f.y - bfhi_f(hp);
        const uint32_t lp = pkbf(ry, rx);
        const uint32_t off = (uint32_t)k * 256 + (((uint32_t)n2 * 4) ^ ((k & 7) << 4));
        *(uint32_t*)(smp + OFF_WHI + off) = hp;
        *(uint32_t*)(smp + OFF_WLO + off) = lp;
    }
    __syncthreads();   // W2 tiles ready for all warps' stage 3

    // per-lane W1/b1: lane owns dims d0=2*lane, d1=2*lane+1
    const float w10a = W1[2*lane],      w11a = W1[64 + 2*lane];
    const float w10b = W1[2*lane + 1],  w11b = W1[65 + 2*lane];
    const float b1a  = b1[2*lane],      b1b  = b1[2*lane + 1];

    // stage-1 sparse row of this lane (lane == target node t)
    int s0 = 0, s1 = 0, s2 = 0;
    float aw0 = 0.f, aw1 = 0.f, aw2 = 0.f;
    if (lane < 21) {
        s0  = cIdx[lane*3];  s1  = cIdx[lane*3+1];  s2  = cIdx[lane*3+2];
        aw0 = cWt[lane*3];   aw1 = cWt[lane*3+1];   aw2 = cWt[lane*3+2];
    }

    const int g0 = (blockIdx.x * NWARP + warp) * 16;    // this warp's 16 graphs

    float* const yx = (float*)(smp + OFF_YX) + warp * 21 * 16;   // [t][g]
    float* const yy = (float*)(smp + OFF_YY) + warp * 21 * 16;

    // ---- stage 1: y = A_norm @ x via shuffles, 4 quads of graphs ----
    #pragma unroll
    for (int h = 0; h < 4; h++) {
        float2 xv[4];
        #pragma unroll
        for (int j = 0; j < 4; j++) {
            const int g = g0 + 4*h + j;
            xv[j] = (lane < 21 && g < G)
                    ? ((const float2*)x)[(size_t)g * 21 + lane]
                    : make_float2(0.f, 0.f);
        }
        float ax[4], ay[4];
        #pragma unroll
        for (int j = 0; j < 4; j++) {
            float xs0x = __shfl_sync(FULLMASK, xv[j].x, s0);
            float xs0y = __shfl_sync(FULLMASK, xv[j].y, s0);
            float xs1x = __shfl_sync(FULLMASK, xv[j].x, s1);
            float xs1y = __shfl_sync(FULLMASK, xv[j].y, s1);
            float xs2x = __shfl_sync(FULLMASK, xv[j].x, s2);
            float xs2y = __shfl_sync(FULLMASK, xv[j].y, s2);
            ax[j] = fmaf(aw2, xs2x, fmaf(aw1, xs1x, aw0 * xs0x));
            ay[j] = fmaf(aw2, xs2y, fmaf(aw1, xs1y, aw0 * xs0y));
        }
        if (lane < 21) {
            *(float4*)&yx[lane * 16 + 4*h] = make_float4(ax[0], ax[1], ax[2], ax[3]);
            *(float4*)&yy[lane * 16 + 4*h] = make_float4(ay[0], ay[1], ay[2], ay[3]);
        }
    }
    __syncwarp();

    // ---- stage 2: p[g][d0..d1] = sum_t c_t relu(y@W1+b1), 16 graphs ----
    float p0[16], p1[16];
    #pragma unroll
    for (int g = 0; g < 16; g++) { p0[g] = 0.f; p1[g] = 0.f; }

    #pragma unroll 3
    for (int t = 0; t < 21; t++) {
        const float ct = cPool[t];
        float4 qx[4], qy[4];
        #pragma unroll
        for (int q = 0; q < 4; q++) {
            qx[q] = *(const float4*)&yx[t * 16 + 4*q];
            qy[q] = *(const float4*)&yy[t * 16 + 4*q];
        }
        #pragma unroll
        for (int q = 0; q < 4; q++) {
            const float xs[4] = {qx[q].x, qx[q].y, qx[q].z, qx[q].w};
            const float ys[4] = {qy[q].x, qy[q].y, qy[q].z, qy[q].w};
            #pragma unroll
            for (int j = 0; j < 4; j++) {
                const int g = 4*q + j;
                float ha = fmaf(ys[j], w11a, fmaf(xs[j], w10a, b1a));
                ha = fmaxf(ha, 0.f);
                p0[g] = fmaf(ct, ha, p0[g]);
                float hb = fmaf(ys[j], w11b, fmaf(xs[j], w10b, b1b));
                hb = fmaxf(hb, 0.f);
                p1[g] = fmaf(ct, hb, p1[g]);
            }
        }
    }

    // ---- write A tile: p -> bf16 hi/lo, swizzled [16 rows][128B] per warp ----
    {
        char* const Ahi = smp + OFF_AHI + warp * 2048;
        char* const Alo = smp + OFF_ALO + warp * 2048;
        #pragma unroll
        for (int g = 0; g < 16; g++) {
            const uint32_t hp = pkbf(p1[g], p0[g]);
            const float r0 = p0[g] - bflo_f(hp);
            const float r1 = p1[g] - bfhi_f(hp);
            const uint32_t lp = pkbf(r1, r0);
            const uint32_t off = (uint32_t)g * 128 + (((uint32_t)lane * 4) ^ ((g & 7) << 4));
            *(uint32_t*)(Ahi + off) = hp;
            *(uint32_t*)(Alo + off) = lp;
        }
    }
    __syncwarp();

    // ---- stage 3: out[16x128] = p @ W2 + b2 via mma.sync (3-pass hi/lo) ----
    // A fragments: m = lane&15, 16B-chunk = lane>>4
    uint32_t ahi[4][4], alo[4][4];
    {
        const uint32_t m = lane & 15, ch = (lane >> 4);
        const uint32_t arow = m * 128;
        const uint32_t abase_hi = sbase + OFF_AHI + warp * 2048;
        const uint32_t abase_lo = sbase + OFF_ALO + warp * 2048;
        #pragma unroll
        for (int kt = 0; kt < 4; kt++) {
            const uint32_t kb = (uint32_t)kt * 32 + ch * 16;
            const uint32_t off = arow + (kb ^ ((m & 7) << 4));
            ldsm_x4(ahi[kt], abase_hi + off);
            ldsm_x4(alo[kt], abase_lo + off);
        }
    }

    const uint32_t bk   = lane & 15;                  // B ldsm row within k16
    const uint32_t wbase_hi = sbase + OFF_WHI;
    const uint32_t wbase_lo = sbase + OFF_WLO;
    const int gr0 = g0 + (lane >> 2);
    const int gr1 = gr0 + 8;
    const int ncol = (lane & 3) * 2;

    #pragma unroll 4
    for (int nt = 0; nt < 16; nt++) {
        float d[4] = {0.f, 0.f, 0.f, 0.f};
        const uint32_t nb = (uint32_t)nt * 16;
        #pragma unroll
        for (int kt = 0; kt < 4; kt++) {
            const uint32_t k = (uint32_t)kt * 16 + bk;
            const uint32_t off = k * 256 + (nb ^ ((k & 7) << 4));
            uint32_t bh0, bh1, bl0, bl1;
            ldsm_x2t(bh0, bh1, wbase_hi + off);
            ldsm_x2t(bl0, bl1, wbase_lo + off);
            mma16816(d, ahi[kt], bh0, bh1);
            mma16816(d, alo[kt], bh0, bh1);
            mma16816(d, ahi[kt], bl0, bl1);
        }
        // epilogue: D rows (gr0, gr1), cols nt*8 + ncol (+1)
        const int c = nt * 8 + ncol;
        const float2 bb = __ldg((const float2*)(b2 + c));
        if (gr0 < G)
            *(float2*)(out + (size_t)gr0 * 128 + c) = make_float2(d[0] + bb.x, d[1] + bb.y);
        if (gr1 < G)
            *(float2*)(out + (size_t)gr1 * 128 + c) = make_float2(d[2] + bb.x, d[3] + bb.y);
    }
}

extern "C" void kernel_launch(void* const* d_in, const int* in_sizes, int n_in,
                              void* d_out, int out_size) {
    const float* x  = (const float*)d_in[0];
    const float* W1 = (const float*)d_in[1];
    const float* b1 = (const float*)d_in[2];
    const float* W2 = (const float*)d_in[3];
    const float* b2 = (const float*)d_in[4];
    float* out = (float*)d_out;

    const int G = in_sizes[0] / 42;              // graphs = B*S = 32768
    const int blocks = (G + 127) / 128;          // 16 graphs/warp * 8 warps/CTA

    static int attr_set = 0;
    if (!attr_set) {
        cudaFuncSetAttribute(gnn_kernel,
                             cudaFuncAttributeMaxDynamicSharedMemorySize, DYN_SMEM);
        attr_set = 1;
    }
    gnn_kernel<<<blocks, THREADS, DYN_SMEM>>>(x, W1, b1, W2, b2, out, G);
}